// round 17
// baseline (speedup 1.0000x reference)
#include <cuda_runtime.h>

#define NUM_RBF 64
#define CUTOFF  5.0f
#define MAX_G   64
#define BLOCK   896
#define NWARPS  (BLOCK / 32)
#define QCAP    160         // per-warp queue entries; max fill 31+128=159
#define NCTAS   148
#define WSTRIDE 68          // 64 + 4 pad floats
#define PBLK    256
#define FULLM   0xffffffffu

// Packed node data: {x,y,z, bits(type | batch<<5)}.
__device__ __align__(16) float4 g_pos4[65536];

__global__ void __launch_bounds__(PBLK) prep_kernel(
        const float* __restrict__ pos,
        const int*   __restrict__ types,
        const int*   __restrict__ batch,
        float*       __restrict__ out,
        int N, int G) {
    __shared__ float spos[PBLK * 3];
    int tid  = threadIdx.x;
    int base = blockIdx.x * PBLK;
    int gi   = base + tid;

    if (blockIdx.x == 0 && tid < G) out[tid] = 0.0f;   // d_out poisoned; zero it

    int fbase = base * 3;
    int nf    = min(PBLK * 3, N * 3 - fbase);
    #pragma unroll
    for (int k = 0; k < 3; ++k) {
        int o = k * PBLK + tid;
        if (o < nf) spos[o] = pos[fbase + o];
    }
    __syncthreads();

    if (gi < N) {
        float4 p;
        p.x = spos[tid * 3 + 0];
        p.y = spos[tid * 3 + 1];
        p.z = spos[tid * 3 + 2];
        p.w = __int_as_float((types[gi] & 31) | ((batch[gi] & 63) << 5));
        g_pos4[gi] = p;
    }
}

extern __shared__ float s_dyn[];

// DELTA = 5/63 split hi+lo; GAMMA=(64/5)^2; TWOGD=2*gamma*DELTA; GD2=gamma*DELTA^2;
// CMUL=exp(-2*gamma*DELTA^2).
#define F_DH      0.0793650793650794f
#define F_DL      ((float)(5.0 / 63.0 - (double)0.0793650793650794f))
#define F_INVD    12.6f
#define F_GAMMA   163.84f
#define F_GD2     1.0319979843990426f
#define F_TWOGD   26.006349206349206f
#define F_CMUL    0.1268725387859556f
#define F_PIOC    0.6283185307179586f

// Filtered-RBF dot product for one edge. wp = smem table row base (unshifted).
__device__ __forceinline__ float ladder_eval(float d, const float* __restrict__ wp) {
    // Fixed 12-mu window of 3 aligned quads covering mus within +-4*DELTA of d.
    int mc = (int)(d * F_INVD);
    int q0 = min(13, max(0, mc - 4) >> 2);
    wp += q0 * 4;

    // Two direct seeds at window slots 5/6 (split-DELTA offsets), outward chains.
    float i5 = (float)(q0 * 4 + 5);
    float i6 = i5 + 1.0f;
    float x5 = fmaf(i5, -F_DH, d); x5 = fmaf(i5, -F_DL, x5);
    float x6 = fmaf(i6, -F_DH, d); x6 = fmaf(i6, -F_DL, x6);
    float e5 = __expf(-F_GAMMA * x5 * x5);
    float e6 = __expf(-F_GAMMA * x6 * x6);
    float ru = __expf(fmaf( F_TWOGD, x6, -F_GD2));
    float rd = __expf(fmaf(-F_TWOGD, x5, -F_GD2));

    float4 w0 = *(const float4*)(wp);
    float4 w1 = *(const float4*)(wp + 4);
    float4 w2 = *(const float4*)(wp + 8);

    float acc = fmaf(w1.z, e6, w1.y * e5);                   // k=5,6
    float e = e6, r = ru;                                    // upward from 6
    e *= r; acc = fmaf(w1.w, e, acc); r *= F_CMUL;           // k=7
    e *= r; acc = fmaf(w2.x, e, acc); r *= F_CMUL;           // k=8
    e *= r; acc = fmaf(w2.y, e, acc); r *= F_CMUL;           // k=9
    e *= r; acc = fmaf(w2.z, e, acc); r *= F_CMUL;           // k=10
    e *= r; acc = fmaf(w2.w, e, acc);                        // k=11
    e = e5; r = rd;                                          // downward from 5
    e *= r; acc = fmaf(w1.x, e, acc); r *= F_CMUL;           // k=4
    e *= r; acc = fmaf(w0.w, e, acc); r *= F_CMUL;           // k=3
    e *= r; acc = fmaf(w0.z, e, acc); r *= F_CMUL;           // k=2
    e *= r; acc = fmaf(w0.y, e, acc); r *= F_CMUL;           // k=1
    e *= r; acc = fmaf(w0.x, e, acc);                        // k=0

    float fc = 0.5f * (__cosf(F_PIOC * d) + 1.0f);
    return acc * fc;
}

__global__ void __launch_bounds__(BLOCK, 1) edge_kernel(
        const int*   __restrict__ ei,
        const float* __restrict__ rbf,
        const float* __restrict__ filt,
        float*       __restrict__ out,
        int E, int T) {
    const int rows = T * T;
    float* sw  = s_dyn;                   // rows * WSTRIDE floats
    float* esm = s_dyn + rows * WSTRIDE;  // 64 graph bins
    // Per-warp survivor queues, 8B entries {d_bits, base<<6|g}.
    uint2* qbase = (uint2*)(s_dyn + rows * WSTRIDE + MAX_G);
    int tid  = threadIdx.x;
    int lane = tid & 31;
    uint2* q = qbase + (tid >> 5) * QCAP;

    // Build fused weight table (rbf * filt) in smem, padded stride.
    int nq = rows * (NUM_RBF / 4);
    for (int idx = tid; idx < nq; idx += BLOCK) {
        int r = idx >> 4, c = idx & 15;
        float4 va = __ldg((const float4*)rbf + idx);
        float4 vb = __ldg((const float4*)filt + idx);
        float4 w;
        w.x = va.x * vb.x; w.y = va.y * vb.y;
        w.z = va.z * vb.z; w.w = va.w * vb.w;
        *(float4*)&sw[r * WSTRIDE + c * 4] = w;
    }
    if (tid < MAX_G) esm[tid] = 0.0f;
    __syncthreads();

    if ((E & 3) == 0) {
        const int nquad  = E >> 2;
        const int stride = NCTAS * BLOCK;
        const int4* s4p = (const int4*)ei;
        const int4* d4p = (const int4*)(ei + E);
        const unsigned lmlt = (1u << lane) - 1u;
        unsigned cnt = 0;                 // warp-uniform queue fill

        int i = blockIdx.x * BLOCK + tid;
        for (; __any_sync(FULLM, i < nquad); i += stride) {
            bool valid = i < nquad;
            int rdidx = valid ? i : 0;
            int4 s4 = __ldg(s4p + rdidx);
            int4 d4 = __ldg(d4p + rdidx);
            // 8 gathers issued up front (MLP 8).
            float4 a0 = __ldg(&g_pos4[s4.x]);
            float4 b0 = __ldg(&g_pos4[d4.x]);
            float4 a1 = __ldg(&g_pos4[s4.y]);
            float4 b1 = __ldg(&g_pos4[d4.y]);
            float4 a2 = __ldg(&g_pos4[s4.z]);
            float4 b2 = __ldg(&g_pos4[d4.z]);
            float4 a3 = __ldg(&g_pos4[s4.w]);
            float4 b3 = __ldg(&g_pos4[d4.w]);

            // d-phase + warp-compacted append of survivors.
            #define SLOT(AA, BB)                                                 \
            {                                                                    \
                float dx = BB.x - AA.x, dy = BB.y - AA.y, dz = BB.z - AA.z;      \
                float d = sqrtf(dx * dx + dy * dy + dz * dz + 1e-12f);           \
                bool p = valid && (d < CUTOFF);                                  \
                unsigned bal = __ballot_sync(FULLM, p);                          \
                if (p) {                                                         \
                    int ab = __float_as_int(AA.w);                               \
                    int bbw = __float_as_int(BB.w);                              \
                    int ta = ab & 31, tb = bbw & 31;                             \
                    int lo = min(ta, tb), hi = max(ta, tb);                      \
                    unsigned pk = ((unsigned)((lo * T + hi) * WSTRIDE) << 6)     \
                                | (unsigned)((ab >> 5) & 63);                    \
                    q[cnt + __popc(bal & lmlt)] =                                \
                        make_uint2(__float_as_uint(d), pk);                      \
                }                                                                \
                cnt += (unsigned)__popc(bal);                                    \
            }
            SLOT(a0, b0)
            SLOT(a1, b1)
            SLOT(a2, b2)
            SLOT(a3, b3)
            #undef SLOT

            // Drain in full-width chunks of 32 (warp-uniform).
            while (cnt >= 32) {
                cnt -= 32;
                uint2 en = q[cnt + lane];
                float d = __uint_as_float(en.x);
                float v = ladder_eval(d, sw + (en.y >> 6));
                atomicAdd(&esm[en.y & 63], v);
            }
        }
        // Tail drain (< 32 entries).
        if (lane < cnt) {
            uint2 en = q[lane];
            float d = __uint_as_float(en.x);
            float v = ladder_eval(d, sw + (en.y >> 6));
            atomicAdd(&esm[en.y & 63], v);
        }
    } else {
        for (int e = blockIdx.x * BLOCK + tid; e < E; e += NCTAS * BLOCK) {
            int src = __ldg(ei + e);
            int dst = __ldg(ei + e + E);
            float4 a = __ldg(&g_pos4[src]);
            float4 b = __ldg(&g_pos4[dst]);
            float dx = b.x - a.x, dy = b.y - a.y, dz = b.z - a.z;
            float d = sqrtf(dx * dx + dy * dy + dz * dz + 1e-12f);
            if (d < CUTOFF) {
                int ab = __float_as_int(a.w);
                int bw = __float_as_int(b.w);
                int ta = ab & 31, tb = bw & 31;
                int lo = min(ta, tb), hi = max(ta, tb);
                float v = ladder_eval(d, sw + (lo * T + hi) * WSTRIDE);
                atomicAdd(&esm[(ab >> 5) & 63], v);
            }
        }
    }

    __syncthreads();
    if (tid < MAX_G) atomicAdd(&out[tid], esm[tid]);
}

extern "C" void kernel_launch(void* const* d_in, const int* in_sizes, int n_in,
                              void* d_out, int out_size) {
    const float* pos   = (const float*)d_in[0];
    const float* rbf   = (const float*)d_in[1];
    const float* filt  = (const float*)d_in[2];
    const int*   ei    = (const int*)d_in[3];
    const int*   types = (const int*)d_in[4];
    const int*   batch = (const int*)d_in[5];

    int N  = in_sizes[0] / 3;
    int WN = in_sizes[1];
    int E  = in_sizes[3] / 2;
    int G  = out_size < MAX_G ? out_size : MAX_G;

    int T = 1;
    while (T * T * NUM_RBF < WN) T++;      // 25 for this dataset

    int smem_bytes = (T * T * WSTRIDE + MAX_G) * 4 + NWARPS * QCAP * 8;
    cudaFuncSetAttribute(edge_kernel,
                         cudaFuncAttributeMaxDynamicSharedMemorySize, smem_bytes);

    int prep_blocks = (N + PBLK - 1) / PBLK;
    prep_kernel<<<prep_blocks, PBLK>>>(pos, types, batch, (float*)d_out, N, G);
    edge_kernel<<<NCTAS, BLOCK, smem_bytes>>>(ei, rbf, filt, (float*)d_out, E, T);
}